// round 8
// baseline (speedup 1.0000x reference)
#include <cuda_runtime.h>
#include <cuda_fp16.h>
#include <stdint.h>

#define B_    8
#define NV_   128
#define NQ_   512
#define DIN   128
#define DPROJ 512
#define HD    256

#define PR_S  136
#define VW_S  264
#define SC_S  132
#define EB_S  136
#define VT_S  136

#define NCTA  128

// ---- device scratch (allocations forbidden) ----
__device__ __half g_q16 [B_*NQ_*DPROJ];
__device__ __half g_vw16[B_*NV_*DPROJ];
__device__ __half g_vT16[B_*DPROJ*NV_];
__device__ __half g_WvT [DPROJ*DIN];
__device__ __half g_WqT [DPROJ*DIN];
__device__ float  g_head[B_*DPROJ];
__device__ float  g_dummy[32];
__device__ unsigned g_barC[4];   // accumulating barrier counters (replay-safe)

__device__ __forceinline__ void mma16816(float* c, const uint32_t* a, const uint32_t* b) {
    asm volatile(
        "mma.sync.aligned.m16n8k16.row.col.f32.f16.f16.f32 "
        "{%0,%1,%2,%3}, {%4,%5,%6,%7}, {%8,%9}, {%0,%1,%2,%3};\n"
        : "+f"(c[0]), "+f"(c[1]), "+f"(c[2]), "+f"(c[3])
        : "r"(a[0]), "r"(a[1]), "r"(a[2]), "r"(a[3]), "r"(b[0]), "r"(b[1]));
}

// Grid-wide barrier: every replay adds exactly NCTA arrivals per slot, so
// cohorts align to multiples of NCTA and the counter never needs resetting.
__device__ __forceinline__ void grid_barrier(int slot) {
    __threadfence();
    __syncthreads();
    if (threadIdx.x == 0) {
        unsigned my = atomicAdd(&g_barC[slot], 1u);
        unsigned tgt = (my / NCTA + 1u) * NCTA;
        unsigned cur;
        do {
            asm volatile("ld.acquire.gpu.u32 %0, [%1];"
                         : "=r"(cur) : "l"(g_barC + slot));
        } while (cur < tgt);
    }
    __syncthreads();
}

__global__ __launch_bounds__(512, 1) void ban_k(
    const float* __restrict__ v,  const float* __restrict__ q,
    const float* __restrict__ Wv, const float* __restrict__ Wq,
    const float* __restrict__ bv, const float* __restrict__ bq,
    const float* __restrict__ wa, const float* __restrict__ Wo,
    const float* __restrict__ bo, float* __restrict__ out)
{
    extern __shared__ __align__(16) char smem[];
    int t = threadIdx.x, bid = blockIdx.x;
    int lane = t & 31, wid = t >> 5;
    int lr = lane >> 2, lc = (lane & 3)*2;
    float* att_out = out + B_*HD;

    // ================= phase 0: W transpose + zero + Wo prefetch =================
    if (bid < 16) {
        __half* s = (__half*)smem;                        // [64][136]
        const float* W = (bid & 8) ? Wq : Wv;
        __half* WT = (bid & 8) ? g_WqT : g_WvT;
        int n0 = (bid & 7) * 64;
        #pragma unroll
        for (int it = 0; it < 16; it++) {
            int fi = t + it*512;                          // 8192 elems
            int k = fi >> 6, nn = fi & 63;
            s[nn*136 + k] = __float2half(W[(size_t)k*DPROJ + n0 + nn]);
        }
        __syncthreads();
        #pragma unroll
        for (int it = 0; it < 2; it++) {
            int fi = t + it*512;                          // 1024 float4
            int n = fi >> 4, kq = (fi & 15)*8;
            *(float4*)(WT + (size_t)(n0 + n)*DIN + kq) = *(const float4*)(s + n*136 + kq);
        }
    } else if (bid == 16) {
        #pragma unroll
        for (int it = 0; it < 8; it++) g_head[t + it*512] = 0.f;
    } else if (bid == 17) {
        #pragma unroll
        for (int it = 0; it < 4; it++) out[t + it*512] = 0.f;
    } else {
        const float4* wo4 = (const float4*)Wo;            // L2 prefetch 512KB
        float acc = 0.f;
        for (int idx = (bid - 18)*512 + t; idx < 32768; idx += 110*512) {
            float4 f = wo4[idx];
            acc += f.x + f.y + f.z + f.w;
        }
        if (__float_as_uint(acc) == 0xdeadbeefu) g_dummy[t & 31] = acc;
    }
    grid_barrier(0);

    // ================= phase 1: projections (160 jobs over 128 CTAs) =================
    {
        __half* As = (__half*)smem;                       // [128][136]
        __half* Bs = (__half*)(smem + 128*PR_S*2);        // [128][136]
        for (int job = bid; job < 160; job += NCTA) {
            bool isV = job < 32;
            int bn, bm;
            if (isV) { bn = (job & 3)*128;  bm = (job >> 2)*128; }
            else     { int j2 = job - 32; bn = (j2 & 3)*128; bm = (j2 >> 2)*128; }
            const float* A    = isV ? v  : q;
            const float* bias = isV ? bv : bq;
            const __half* WT  = isV ? g_WvT : g_WqT;

            #pragma unroll
            for (int it = 0; it < 8; it++) {
                int fi = t + it*512;
                int m = fi >> 5, k = (fi & 31)*4;
                float4 f = *(const float4*)(A + (size_t)(bm+m)*DIN + k);
                __half2 h0 = __floats2half2_rn(f.x, f.y);
                __half2 h1 = __floats2half2_rn(f.z, f.w);
                uint2 u; u.x = *(uint32_t*)&h0; u.y = *(uint32_t*)&h1;
                *(uint2*)(As + m*PR_S + k) = u;
            }
            #pragma unroll
            for (int it = 0; it < 4; it++) {
                int fi = t + it*512;
                int n = fi >> 4, k = (fi & 15)*8;
                *(float4*)(Bs + n*PR_S + k) = *(const float4*)(WT + (size_t)(bn+n)*DIN + k);
            }
            __syncthreads();

            int warpM = wid >> 2, warpN = wid & 3;
            float acc[2][4][4] = {};
            #pragma unroll
            for (int ks = 0; ks < 8; ks++) {
                int k0 = ks*16;
                uint32_t a[2][4], b[4][2];
                #pragma unroll
                for (int mt = 0; mt < 2; mt++) {
                    const __half* ab = As + (warpM*32 + mt*16 + lr)*PR_S + k0 + lc;
                    a[mt][0] = *(const uint32_t*)ab;
                    a[mt][1] = *(const uint32_t*)(ab + 8*PR_S);
                    a[mt][2] = *(const uint32_t*)(ab + 8);
                    a[mt][3] = *(const uint32_t*)(ab + 8*PR_S + 8);
                }
                #pragma unroll
                for (int nt = 0; nt < 4; nt++) {
                    const __half* bb = Bs + (warpN*32 + nt*8 + lr)*PR_S + k0 + lc;
                    b[nt][0] = *(const uint32_t*)bb;
                    b[nt][1] = *(const uint32_t*)(bb + 8);
                }
                #pragma unroll
                for (int mt = 0; mt < 2; mt++)
                    #pragma unroll
                    for (int nt = 0; nt < 4; nt++)
                        mma16816(acc[mt][nt], a[mt], b[nt]);
            }

            if (isV) __syncthreads();   // As reused as transpose staging

            #pragma unroll
            for (int mt = 0; mt < 2; mt++) {
                int rowL = warpM*32 + mt*16 + lr;
                #pragma unroll
                for (int nt = 0; nt < 4; nt++) {
                    int colL = warpN*32 + nt*8 + lc;
                    int col = bn + colL;
                    float b0 = bias[col], b1 = bias[col+1];
                    float v00 = acc[mt][nt][0] + b0, v01 = acc[mt][nt][1] + b1;
                    float v10 = acc[mt][nt][2] + b0, v11 = acc[mt][nt][3] + b1;
                    int row = bm + rowL;
                    if (!isV) {
                        *(__half2*)(g_q16 + (size_t)row*DPROJ + col) =
                            __floats2half2_rn(v00, v01);
                        *(__half2*)(g_q16 + (size_t)(row+8)*DPROJ + col) =
                            __floats2half2_rn(v10, v11);
                    } else {
                        float w0 = wa[col & 255], w1 = wa[(col+1) & 255];
                        *(__half2*)(g_vw16 + (size_t)row*DPROJ + col) =
                            __floats2half2_rn(v00*w0, v01*w1);
                        *(__half2*)(g_vw16 + (size_t)(row+8)*DPROJ + col) =
                            __floats2half2_rn(v10*w0, v11*w1);
                        __half* tr = As;
                        tr[colL*PR_S + rowL]       = __float2half(v00);
                        tr[(colL+1)*PR_S + rowL]   = __float2half(v01);
                        tr[colL*PR_S + rowL+8]     = __float2half(v10);
                        tr[(colL+1)*PR_S + rowL+8] = __float2half(v11);
                    }
                }
            }

            if (isV) {
                __syncthreads();
                const __half* tr = As;
                int b = (job >> 2);
                #pragma unroll
                for (int it = 0; it < 4; it++) {
                    int fi = t + it*512;
                    int n = fi >> 4, k = (fi & 15)*8;
                    *(float4*)(g_vT16 + ((size_t)b*DPROJ + bn + n)*NV_ + k) =
                        *(const float4*)(tr + n*PR_S + k);
                }
            }
            __syncthreads();   // protect smem reuse across loop iterations
        }
    }
    grid_barrier(1);

    // ================= phase 2: score + softmax + att + head (1 job/CTA) ============
    {
        __half* vws = (__half*)smem;
        __half* qs  = (__half*)(smem + 69632);
        float*  sc  = (float*) (smem + 103424);
        __half* ebf = (__half*)(smem + 137216);
        float*  inv = (float*) (smem + 154624);

        int jt = bid & 7, h = (bid >> 3) & 1, b = bid >> 4;

        const __half* vwg = g_vw16 + ((size_t)b*NV_)*DPROJ + h*HD;
        const __half* qg  = g_q16  + ((size_t)(b*NQ_ + jt*64))*DPROJ + h*HD;

        #pragma unroll
        for (int it = 0; it < 8; it++) {
            int fi = t + it*512;
            int i = fi >> 5, k = (fi & 31)*8;
            *(float4*)(vws + i*VW_S + k) = *(const float4*)(vwg + (size_t)i*DPROJ + k);
        }
        #pragma unroll
        for (int it = 0; it < 4; it++) {
            int fi = t + it*512;
            int j = fi >> 5, k = (fi & 31)*8;
            *(float4*)(qs + j*VW_S + k) = *(const float4*)(qg + (size_t)j*DPROJ + k);
        }
        __syncthreads();

        // phase 1 mma
        {
            int iw = (wid >> 2)*32, jw = (wid & 3)*16;
            float acc[2][2][4] = {};
            #pragma unroll
            for (int ks = 0; ks < 16; ks++) {
                int k0 = ks*16;
                uint32_t a[2][4], bq2[2][2];
                #pragma unroll
                for (int mi = 0; mi < 2; mi++) {
                    const __half* ab = vws + (iw + mi*16 + lr)*VW_S + k0 + lc;
                    a[mi][0] = *(const uint32_t*)ab;
                    a[mi][1] = *(const uint32_t*)(ab + 8*VW_S);
                    a[mi][2] = *(const uint32_t*)(ab + 8);
                    a[mi][3] = *(const uint32_t*)(ab + 8*VW_S + 8);
                }
                #pragma unroll
                for (int nj = 0; nj < 2; nj++) {
                    const __half* bb = qs + (jw + nj*8 + lr)*VW_S + k0 + lc;
                    bq2[nj][0] = *(const uint32_t*)bb;
                    bq2[nj][1] = *(const uint32_t*)(bb + 8);
                }
                #pragma unroll
                for (int mi = 0; mi < 2; mi++)
                    #pragma unroll
                    for (int nj = 0; nj < 2; nj++)
                        mma16816(acc[mi][nj], a[mi], bq2[nj]);
            }
            #pragma unroll
            for (int mi = 0; mi < 2; mi++) {
                int i0 = iw + mi*16 + lr;
                #pragma unroll
                for (int nj = 0; nj < 2; nj++) {
                    int j0 = jw + nj*8 + lc;
                    sc[j0*SC_S + i0]       = acc[mi][nj][0];
                    sc[(j0+1)*SC_S + i0]   = acc[mi][nj][1];
                    sc[j0*SC_S + i0+8]     = acc[mi][nj][2];
                    sc[(j0+1)*SC_S + i0+8] = acc[mi][nj][3];
                }
            }
        }
        __syncthreads();

        // softmax over i
        #pragma unroll
        for (int rr = 0; rr < 4; rr++) {
            int j = wid*4 + rr;
            float4 x = *(float4*)(sc + j*SC_S + lane*4);
            float mx = fmaxf(fmaxf(x.x, x.y), fmaxf(x.z, x.w));
            #pragma unroll
            for (int off = 16; off; off >>= 1)
                mx = fmaxf(mx, __shfl_xor_sync(0xffffffffu, mx, off));
            float4 e;
            e.x = __expf(x.x - mx); e.y = __expf(x.y - mx);
            e.z = __expf(x.z - mx); e.w = __expf(x.w - mx);
            float s = e.x + e.y + e.z + e.w;
            #pragma unroll
            for (int off = 16; off; off >>= 1)
                s += __shfl_xor_sync(0xffffffffu, s, off);
            *(float4*)(sc + j*SC_S + lane*4) = e;
            *(__half2*)(ebf + j*EB_S + lane*4)     = __floats2half2_rn(e.x, e.y);
            *(__half2*)(ebf + j*EB_S + lane*4 + 2) = __floats2half2_rn(e.z, e.w);
            if (lane == 0) inv[j] = 1.0f / s;
        }
        __syncthreads();

        // load vT (overwrites vws) + write att
        const __half* vtg = g_vT16 + ((size_t)b*DPROJ + h*HD)*NV_;
        #pragma unroll
        for (int it = 0; it < 8; it++) {
            int fi = t + it*512;
            int d = fi >> 4, k = (fi & 15)*8;
            *(float4*)(vws + d*VT_S + k) = *(const float4*)(vtg + (size_t)d*NV_ + k);
        }
        float* attp = att_out + ((size_t)(b*2 + h)*NV_)*NQ_ + jt*64;
        #pragma unroll
        for (int it = 0; it < 16; it++) {
            int e = it*512 + t;
            int i = e >> 6, j = e & 63;
            attp[(size_t)i*NQ_ + j] = sc[j*SC_S + i] * inv[j];
        }
        __syncthreads();

        // phase 2 mma + head atomics
        {
            int jw2 = (wid >> 3)*32, dw = (wid & 7)*32;
            float acc[2][4][4] = {};
            #pragma unroll
            for (int ks = 0; ks < 8; ks++) {
                int k0 = ks*16;
                uint32_t a[2][4], bvv[4][2];
                #pragma unroll
                for (int mi = 0; mi < 2; mi++) {
                    const __half* ab = ebf + (jw2 + mi*16 + lr)*EB_S + k0 + lc;
                    a[mi][0] = *(const uint32_t*)ab;
                    a[mi][1] = *(const uint32_t*)(ab + 8*EB_S);
                    a[mi][2] = *(const uint32_t*)(ab + 8);
                    a[mi][3] = *(const uint32_t*)(ab + 8*EB_S + 8);
                }
                #pragma unroll
                for (int nt = 0; nt < 4; nt++) {
                    const __half* bb = vws + (dw + nt*8 + lr)*VT_S + k0 + lc;
                    bvv[nt][0] = *(const uint32_t*)bb;
                    bvv[nt][1] = *(const uint32_t*)(bb + 8);
                }
                #pragma unroll
                for (int mi = 0; mi < 2; mi++)
                    #pragma unroll
                    for (int nt = 0; nt < 4; nt++)
                        mma16816(acc[mi][nt], a[mi], bvv[nt]);
            }
            float* headp = g_head + (b*2 + h)*HD;
            #pragma unroll
            for (int nt = 0; nt < 4; nt++) {
                int d0 = dw + nt*8 + lc;
                float va = 0.f, vb = 0.f;
                #pragma unroll
                for (int mi = 0; mi < 2; mi++) {
                    int j0 = jw2 + mi*16 + lr, j1 = j0 + 8;
                    float w0 = inv[j0], w1 = inv[j1];
                    float q00 = __half2float(qs[j0*VW_S + d0]);
                    float q01 = __half2float(qs[j0*VW_S + d0+1]);
                    float q10 = __half2float(qs[j1*VW_S + d0]);
                    float q11 = __half2float(qs[j1*VW_S + d0+1]);
                    va += acc[mi][nt][0]*w0*q00 + acc[mi][nt][2]*w1*q10;
                    vb += acc[mi][nt][1]*w0*q01 + acc[mi][nt][3]*w1*q11;
                }
                va += __shfl_xor_sync(0xffffffffu, va, 4);
                va += __shfl_xor_sync(0xffffffffu, va, 8);
                va += __shfl_xor_sync(0xffffffffu, va, 16);
                vb += __shfl_xor_sync(0xffffffffu, vb, 4);
                vb += __shfl_xor_sync(0xffffffffu, vb, 8);
                vb += __shfl_xor_sync(0xffffffffu, vb, 16);
                if (lr == 0) {
                    atomicAdd(headp + d0,     va);
                    atomicAdd(headp + d0 + 1, vb);
                }
            }
        }
    }
    grid_barrier(2);

    // ================= phase 3: fused output GEMM (1 job/CTA) =================
    {
        float* hsl = (float*)smem;            // [8][32]
        float* red = hsl + 8*32;              // [16][8][32]
        int cb = bid & 7, ks = bid >> 3;      // 8 col blocks x 16 k-slices
        int col = cb*32 + lane;

        if (t < 256) {
            int b = t >> 5, i = t & 31;
            hsl[b*32 + i] = g_head[b*DPROJ + ks*32 + i];
        }
        __syncthreads();

        float acc[8] = {};
        #pragma unroll
        for (int kk = 0; kk < 2; kk++) {
            int k = wid*2 + kk;
            float wv = Wo[(size_t)(ks*32 + k)*HD + col];
            #pragma unroll
            for (int b = 0; b < 8; b++)
                acc[b] += wv * hsl[b*32 + k];
        }
        #pragma unroll
        for (int b = 0; b < 8; b++) red[(wid*8 + b)*32 + lane] = acc[b];
        __syncthreads();

        if (wid < 8) {
            float s = 0.f;
            #pragma unroll
            for (int ww = 0; ww < 16; ww++) s += red[(ww*8 + wid)*32 + lane];
            if (ks == 0) s += bo[col];
            atomicAdd(&out[wid*HD + col], s);
        }
    }
}

// ============================================================
extern "C" void kernel_launch(void* const* d_in, const int* in_sizes, int n_in,
                              void* d_out, int out_size)
{
    const float* v  = (const float*)d_in[0];
    const float* q  = (const float*)d_in[1];
    const float* Wv = (const float*)d_in[2];
    const float* bv = (const float*)d_in[3];
    const float* Wq = (const float*)d_in[4];
    const float* bq = (const float*)d_in[5];
    const float* wa = (const float*)d_in[6];
    // d_in[7] = ba : constant shift before softmax -> drops out
    const float* Wo = (const float*)d_in[8];
    const float* bo = (const float*)d_in[9];
    float* out = (float*)d_out;

    const int SSM = 154880;
    cudaFuncSetAttribute(ban_k, cudaFuncAttributeMaxDynamicSharedMemorySize, SSM);
    ban_k<<<NCTA, 512, SSM>>>(v, q, Wv, Wq, bv, bq, wa, Wo, bo, out);
}